// round 2
// baseline (speedup 1.0000x reference)
#include <cuda_runtime.h>
#include <math.h>

// Problem dims (fixed by reference)
#define B   128
#define N   2048
#define H   768
#define H2  1536
#define S   16          // N-splits for pooling
#define NPS (N / S)     // 128 rows per split
#define FT  16          // features per gemm block
#define LN_EPS 1e-5f

// Scratch (static device globals; no allocation allowed)
__device__ float g_partial[B * S * H];   // 6.3 MB
__device__ float g_pooled[B * H];        // 393 KB
__device__ float g_gh[B * H2];           // gelu(h) 786 KB

// ---------------------------------------------------------------------------
// Kernel 1: partial mean-pool. grid = (S, B), block = 192 threads (x float4).
// Reads 805 MB of v_emb exactly once, fully coalesced (3 KB per n per block).
// ---------------------------------------------------------------------------
__global__ void __launch_bounds__(192) pool_partial(const float* __restrict__ v) {
    const int s = blockIdx.x;
    const int b = blockIdx.y;
    const int t = threadIdx.x;              // 0..191, 192*4 = 768 = H

    const float4* p = reinterpret_cast<const float4*>(
        v + ((size_t)b * N + (size_t)s * NPS) * H) + t;
    const int stride = H / 4;               // float4 stride per n

    float4 a0 = make_float4(0.f, 0.f, 0.f, 0.f);
    float4 a1 = make_float4(0.f, 0.f, 0.f, 0.f);
    float4 a2 = make_float4(0.f, 0.f, 0.f, 0.f);
    float4 a3 = make_float4(0.f, 0.f, 0.f, 0.f);

    #pragma unroll 1
    for (int n = 0; n < NPS; n += 4) {
        float4 x0 = p[(n + 0) * stride];
        float4 x1 = p[(n + 1) * stride];
        float4 x2 = p[(n + 2) * stride];
        float4 x3 = p[(n + 3) * stride];
        a0.x += x0.x; a0.y += x0.y; a0.z += x0.z; a0.w += x0.w;
        a1.x += x1.x; a1.y += x1.y; a1.z += x1.z; a1.w += x1.w;
        a2.x += x2.x; a2.y += x2.y; a2.z += x2.z; a2.w += x2.w;
        a3.x += x3.x; a3.y += x3.y; a3.z += x3.z; a3.w += x3.w;
    }
    float4 acc;
    acc.x = (a0.x + a1.x) + (a2.x + a3.x);
    acc.y = (a0.y + a1.y) + (a2.y + a3.y);
    acc.z = (a0.z + a1.z) + (a2.z + a3.z);
    acc.w = (a0.w + a1.w) + (a2.w + a3.w);

    float4* dst = reinterpret_cast<float4*>(g_partial + ((size_t)b * S + s) * H) + t;
    *dst = acc;
}

// ---------------------------------------------------------------------------
// Kernel 2: fold the S partial sums, scale by 1/N. grid = B, block = 192.
// ---------------------------------------------------------------------------
__global__ void __launch_bounds__(192) pool_reduce() {
    const int b = blockIdx.x;
    const int t = threadIdx.x;

    float4 acc = make_float4(0.f, 0.f, 0.f, 0.f);
    #pragma unroll
    for (int s = 0; s < S; s++) {
        float4 x = *(reinterpret_cast<const float4*>(g_partial + ((size_t)b * S + s) * H) + t);
        acc.x += x.x; acc.y += x.y; acc.z += x.z; acc.w += x.w;
    }
    const float inv = 1.0f / (float)N;
    acc.x *= inv; acc.y *= inv; acc.z *= inv; acc.w *= inv;
    *(reinterpret_cast<float4*>(g_pooled + (size_t)b * H) + t) = acc;
}

// ---------------------------------------------------------------------------
// Kernel 3: h = pooled @ W1 + b1, then exact GELU.  Feature-tiled so W1
// (4.7 MB) is streamed from DRAM exactly once across the whole grid.
// grid = H2/FT = 96 blocks, 256 threads. Each thread: 1 feature x 8 batch rows.
// ---------------------------------------------------------------------------
__global__ void __launch_bounds__(256) gemm_gelu(const float* __restrict__ W1,
                                                 const float* __restrict__ b1) {
    __shared__ float sp[32][129];   // pooled^T k-tile: [k][b], pad 129 -> conflict-free
    __shared__ float sw[32][FT];    // W1 tile: [k][f]

    const int fbase = blockIdx.x * FT;
    const int t = threadIdx.x;
    const int f = t & 15;           // feature within tile
    const int g = t >> 4;           // batch group (0..15), 8 rows each

    float acc[8];
    #pragma unroll
    for (int j = 0; j < 8; j++) acc[j] = 0.f;

    for (int kt = 0; kt < H; kt += 32) {
        // load pooled^T tile: 32k x 128b = 4096 floats
        #pragma unroll
        for (int i = t; i < 32 * 128; i += 256) {
            int bb = i >> 5, kk = i & 31;
            sp[kk][bb] = g_pooled[bb * H + kt + kk];
        }
        // load W1 tile: 32k x 16f = 512 floats
        #pragma unroll
        for (int i = t; i < 32 * FT; i += 256) {
            int ff = i & 15, kk = i >> 4;
            sw[kk][ff] = W1[(size_t)(kt + kk) * H2 + fbase + ff];
        }
        __syncthreads();

        #pragma unroll
        for (int k = 0; k < 32; k++) {
            float wv = sw[k][f];
            #pragma unroll
            for (int j = 0; j < 8; j++)
                acc[j] += sp[k][g * 8 + j] * wv;
        }
        __syncthreads();
    }

    #pragma unroll
    for (int j = 0; j < 8; j++) {
        int bb = g * 8 + j;
        float x = acc[j] + b1[fbase + f];
        // exact GELU (matches approximate=False): 0.5*x*(1+erf(x/sqrt(2)))
        float ge = 0.5f * x * (1.0f + erff(x * 0.70710678118654752f));
        g_gh[(size_t)bb * H2 + fbase + f] = ge;
    }
}

// ---------------------------------------------------------------------------
// Kernel 4: per-row LayerNorm + head dot + one-hot logits.
// grid = B, block = 512 (each thread owns 3 of the 1536 features).
// Output layout: d_out[0..B)   = pred  (B,1 flattened)
//                d_out[B .. B+B*16) = logits (B,16 flattened)
// ---------------------------------------------------------------------------
__global__ void __launch_bounds__(512) ln_head(const float* __restrict__ gamma,
                                               const float* __restrict__ beta,
                                               const float* __restrict__ W2,
                                               const float* __restrict__ b2,
                                               float* __restrict__ out) {
    const int b = blockIdx.x;
    const int t = threadIdx.x;          // 0..511
    const float* row = g_gh + (size_t)b * H2;

    float x0 = row[t];
    float x1 = row[t + 512];
    float x2 = row[t + 1024];

    float s  = x0 + x1 + x2;
    float sq = x0 * x0 + x1 * x1 + x2 * x2;

    __shared__ float sA[16], sB[16];
    // warp reduce both
    #pragma unroll
    for (int o = 16; o; o >>= 1) {
        s  += __shfl_xor_sync(0xFFFFFFFFu, s,  o);
        sq += __shfl_xor_sync(0xFFFFFFFFu, sq, o);
    }
    int w = t >> 5, l = t & 31;
    if (l == 0) { sA[w] = s; sB[w] = sq; }
    __syncthreads();
    if (t < 32) {
        float a  = (l < 16) ? sA[l] : 0.f;
        float bq = (l < 16) ? sB[l] : 0.f;
        #pragma unroll
        for (int o = 8; o; o >>= 1) {
            a  += __shfl_xor_sync(0xFFFFFFFFu, a,  o);
            bq += __shfl_xor_sync(0xFFFFFFFFu, bq, o);
        }
        if (l == 0) { sA[0] = a; sB[0] = bq; }
    }
    __syncthreads();

    const float mu  = sA[0] * (1.0f / (float)H2);
    const float var = sB[0] * (1.0f / (float)H2) - mu * mu;
    const float rstd = rsqrtf(var + LN_EPS);

    __syncthreads();   // protect sA/sB reuse below

    float y0 = (x0 - mu) * rstd * gamma[t]        + beta[t];
    float y1 = (x1 - mu) * rstd * gamma[t + 512]  + beta[t + 512];
    float y2 = (x2 - mu) * rstd * gamma[t + 1024] + beta[t + 1024];

    float local = y0 * W2[t] + y1 * W2[t + 512] + y2 * W2[t + 1024];
    #pragma unroll
    for (int o = 16; o; o >>= 1)
        local += __shfl_xor_sync(0xFFFFFFFFu, local, o);
    if (l == 0) sA[w] = local;
    __syncthreads();
    if (t < 32) {
        float a = (l < 16) ? sA[l] : 0.f;
        #pragma unroll
        for (int o = 8; o; o >>= 1)
            a += __shfl_xor_sync(0xFFFFFFFFu, a, o);
        if (l == 0) sA[0] = a;
    }
    __syncthreads();

    const float pred = sA[0] + b2[0];

    if (t == 0) out[b] = pred;

    // one-hot logits: round-half-even to match jnp.round, clamp [0,15]
    if (t < 16) {
        float r = rintf(pred);
        r = fminf(fmaxf(r, 0.f), 15.f);
        int aid = (int)r;
        out[B + b * 16 + t] = (t == aid) ? 1.0f : 0.0f;
    }
}

// ---------------------------------------------------------------------------
extern "C" void kernel_launch(void* const* d_in, const int* in_sizes, int n_in,
                              void* d_out, int out_size) {
    const float* v_emb = (const float*)d_in[0];  // [B,N,H]
    const float* W1    = (const float*)d_in[1];  // [H,2H]
    const float* b1    = (const float*)d_in[2];  // [2H]
    const float* gamma = (const float*)d_in[3];  // [2H]
    const float* beta  = (const float*)d_in[4];  // [2H]
    const float* W2    = (const float*)d_in[5];  // [2H,1]
    const float* b2    = (const float*)d_in[6];  // [1]
    float* out = (float*)d_out;

    pool_partial<<<dim3(S, B), 192>>>(v_emb);
    pool_reduce<<<B, 192>>>();
    gemm_gelu<<<H2 / FT, 256>>>(W1, b1);
    ln_head<<<B, 512>>>(gamma, beta, W2, b2, out);
}